// round 11
// baseline (speedup 1.0000x reference)
#include <cuda_runtime.h>
#include <math.h>

// Problem constants
#define Bc 2
#define Tc 2048
#define Cc 1024
#define Hc 16
#define HDc 64
#define M_ROWS (Bc * Tc)            // 4096
#define QKV_COLS (3 * Cc)           // 3072

// Scratch (device globals)
__device__ float g_qkv[(size_t)M_ROWS * QKV_COLS];   // Q,K tf32-rounded (V region unused)
__device__ float g_vt[(size_t)Bc * Hc * HDc * Tc];   // V transposed [b][h][d][t], tf32
__device__ float g_y[(size_t)M_ROWS * Cc];           // tf32-rounded
__device__ float g_xr[(size_t)M_ROWS * Cc];
__device__ float g_war[(size_t)QKV_COLS * Cc];
__device__ float g_wpr[(size_t)Cc * Cc];

__device__ __forceinline__ unsigned f2tf(float x) {
    unsigned y;
    asm("cvt.rna.tf32.f32 %0, %1;" : "=r"(y) : "f"(x));
    return y;
}

__device__ __forceinline__ void mma_tf32(float c[4], const unsigned a[4], const unsigned b[2]) {
    asm volatile(
        "mma.sync.aligned.m16n8k8.row.col.f32.tf32.tf32.f32 "
        "{%0,%1,%2,%3}, {%4,%5,%6,%7}, {%8,%9}, {%0,%1,%2,%3};\n"
        : "+f"(c[0]), "+f"(c[1]), "+f"(c[2]), "+f"(c[3])
        : "r"(a[0]), "r"(a[1]), "r"(a[2]), "r"(a[3]), "r"(b[0]), "r"(b[1]));
}

__device__ __forceinline__ void ldsm_x4(unsigned r[4], unsigned addr) {
    asm volatile("ldmatrix.sync.aligned.m8n8.x4.shared.b16 {%0,%1,%2,%3}, [%4];"
        : "=r"(r[0]), "=r"(r[1]), "=r"(r[2]), "=r"(r[3]) : "r"(addr));
}

__device__ __forceinline__ void cp16(unsigned dst, const void* src) {
    asm volatile("cp.async.cg.shared.global [%0], [%1], 16;" :: "r"(dst), "l"(src));
}
__device__ __forceinline__ void cp_commit() { asm volatile("cp.async.commit_group;"); }
template <int N> __device__ __forceinline__ void cp_wait() {
    asm volatile("cp.async.wait_group %0;" :: "n"(N));
}

// ---------------------------------------------------------------------------
// Fused elementwise tf32 rounding of x, w_attn, w_proj (one launch)
// ---------------------------------------------------------------------------
#define N4_X  ((M_ROWS * Cc) / 4)
#define N4_WA ((QKV_COLS * Cc) / 4)
#define N4_WP ((Cc * Cc) / 4)

__global__ void round3_kernel(const float* __restrict__ x,
                              const float* __restrict__ wa,
                              const float* __restrict__ wp)
{
    int i = blockIdx.x * blockDim.x + threadIdx.x;
    const float4* src;
    float4* dst;
    int j = i;
    if (j < N4_X) {
        src = (const float4*)x;  dst = (float4*)g_xr;
    } else if ((j -= N4_X) < N4_WA) {
        src = (const float4*)wa; dst = (float4*)g_war;
    } else if ((j -= N4_WA) < N4_WP) {
        src = (const float4*)wp; dst = (float4*)g_wpr;
    } else {
        return;
    }
    float4 v = src[j];
    v.x = __uint_as_float(f2tf(v.x));
    v.y = __uint_as_float(f2tf(v.y));
    v.z = __uint_as_float(f2tf(v.z));
    v.w = __uint_as_float(f2tf(v.w));
    dst[j] = v;
}

// ---------------------------------------------------------------------------
// TF32 GEMM (R9-proven config): 128x128 tile, 8 warps, 64x32 warp tile,
// KT=16, 4-stage cp.async ring, ldmatrix x4 fragment loads.
// ---------------------------------------------------------------------------
#define SROW 20
#define STGW (128 * SROW)
#define STGB (STGW * 4)
#define NSTG 4
#define GEMM_SMEM (2 * NSTG * STGB)  // 81920 bytes

template <bool ROUND_OUT, bool V_SPLIT>
__device__ __forceinline__ void gemm_tf32_body(
    const float* __restrict__ A, const float* __restrict__ Wt,
    const float* __restrict__ bias, float* __restrict__ C,
    int N, int K)
{
    extern __shared__ unsigned smem[];
    unsigned* As = smem;
    unsigned* Bs = smem + NSTG * STGW;

    const int tid  = threadIdx.x;
    const int lane = tid & 31;
    const int g    = lane >> 2;
    const int t4   = lane & 3;
    const int warp = tid >> 5;          // 0..7
    const int wm   = (warp >> 2) * 64;
    const int wn   = (warp & 3) * 32;
    const int brow = blockIdx.y * 128;
    const int bcol = blockIdx.x * 128;

    const int lr = tid >> 1;
    const int lk = (tid & 1) * 8;
    const float* Asrc = A  + (size_t)(brow + lr) * K + lk;
    const float* Bsrc = Wt + (size_t)(bcol + lr) * K + lk;
    const unsigned aDst = (unsigned)__cvta_generic_to_shared(&As[lr * SROW + lk]);
    const unsigned bDst = (unsigned)__cvta_generic_to_shared(&Bs[lr * SROW + lk]);

    const unsigned aFrag = (unsigned)__cvta_generic_to_shared(
        &As[(wm + (lane & 15)) * SROW + ((lane >> 4) << 2)]);
    const unsigned bFrag = (unsigned)__cvta_generic_to_shared(
        &Bs[(wn + ((lane >> 4) << 3) + (lane & 7)) * SROW + (((lane >> 3) & 1) << 2)]);

    float acc[4][4][4];
#pragma unroll
    for (int f = 0; f < 4; f++)
#pragma unroll
        for (int e = 0; e < 4; e++)
#pragma unroll
            for (int i = 0; i < 4; i++) acc[f][e][i] = 0.0f;

    const int NT = K / 16;

#pragma unroll
    for (int s = 0; s < NSTG - 1; s++) {
        const unsigned off = s * STGB;
        const float* Ap = Asrc + s * 16;
        const float* Bp = Bsrc + s * 16;
        cp16(aDst + off,      Ap);
        cp16(aDst + off + 16, Ap + 4);
        cp16(bDst + off,      Bp);
        cp16(bDst + off + 16, Bp + 4);
        cp_commit();
    }

    for (int t = 0; t < NT; t++) {
        cp_wait<NSTG - 2>();
        __syncthreads();

        if (t + NSTG - 1 < NT) {
            const unsigned off = ((t + NSTG - 1) & (NSTG - 1)) * STGB;
            const float* Ap = Asrc + (size_t)(t + NSTG - 1) * 16;
            const float* Bp = Bsrc + (size_t)(t + NSTG - 1) * 16;
            cp16(aDst + off,      Ap);
            cp16(aDst + off + 16, Ap + 4);
            cp16(bDst + off,      Bp);
            cp16(bDst + off + 16, Bp + 4);
            cp_commit();
        }

        const unsigned curOff = (t & (NSTG - 1)) * STGB;
#pragma unroll
        for (int kb = 0; kb < 2; kb++) {
            unsigned af[4][4], bf[4][2];
#pragma unroll
            for (int f = 0; f < 4; f++)
                ldsm_x4(af[f], aFrag + curOff + f * (16 * SROW * 4) + kb * 32);
#pragma unroll
            for (int p = 0; p < 2; p++) {
                unsigned tmp[4];
                ldsm_x4(tmp, bFrag + curOff + p * (16 * SROW * 4) + kb * 32);
                bf[2 * p][0]     = tmp[0]; bf[2 * p][1]     = tmp[1];
                bf[2 * p + 1][0] = tmp[2]; bf[2 * p + 1][1] = tmp[3];
            }
#pragma unroll
            for (int f = 0; f < 4; f++)
#pragma unroll
                for (int e = 0; e < 4; e++)
                    mma_tf32(acc[f][e], af[f], bf[e]);
        }
    }

    // Epilogue
    if (V_SPLIT && bcol >= 2 * Cc) {
#pragma unroll
        for (int f = 0; f < 4; f++) {
            const int r0 = brow + wm + f * 16 + g;
            const int bb = r0 >> 11;
            const int tt = r0 & (Tc - 1);
#pragma unroll
            for (int e = 0; e < 4; e++) {
                const int c = bcol + wn + e * 8 + t4 * 2;
                const int local = c - 2 * Cc;
                const int hh = local >> 6;
                const int dd = local & 63;
                float v0 = acc[f][e][0] + bias[c];
                float v1 = acc[f][e][1] + bias[c + 1];
                float v2 = acc[f][e][2] + bias[c];
                float v3 = acc[f][e][3] + bias[c + 1];
                v0 = __uint_as_float(f2tf(v0)); v1 = __uint_as_float(f2tf(v1));
                v2 = __uint_as_float(f2tf(v2)); v3 = __uint_as_float(f2tf(v3));
                float* vb = g_vt + ((size_t)(bb * Hc + hh) * HDc + dd) * Tc;
                vb[tt]          = v0;
                vb[Tc + tt]     = v1;
                vb[tt + 8]      = v2;
                vb[Tc + tt + 8] = v3;
            }
        }
        return;
    }

#pragma unroll
    for (int f = 0; f < 4; f++) {
        const int r0 = brow + wm + f * 16 + g;
#pragma unroll
        for (int e = 0; e < 4; e++) {
            const int c = bcol + wn + e * 8 + t4 * 2;
            const float b0v = bias[c];
            const float b1v = bias[c + 1];
            float2 o0, o1;
            o0.x = acc[f][e][0] + b0v;  o0.y = acc[f][e][1] + b1v;
            o1.x = acc[f][e][2] + b0v;  o1.y = acc[f][e][3] + b1v;
            if (ROUND_OUT) {
                o0.x = __uint_as_float(f2tf(o0.x)); o0.y = __uint_as_float(f2tf(o0.y));
                o1.x = __uint_as_float(f2tf(o1.x)); o1.y = __uint_as_float(f2tf(o1.y));
            }
            *(float2*)(&C[(size_t)r0 * N + c]) = o0;
            *(float2*)(&C[(size_t)(r0 + 8) * N + c]) = o1;
        }
    }
}

__global__ __launch_bounds__(256, 2) void qkv_tf32(const float* __restrict__ b)
{
    gemm_tf32_body<true, true>(g_xr, g_war, b, g_qkv, QKV_COLS, Cc);
}

__global__ __launch_bounds__(256, 2) void proj_tf32(const float* __restrict__ b,
                                                    float* __restrict__ out)
{
    gemm_tf32_body<false, false>(g_y, g_wpr, b, out, Cc, Cc);
}

// ---------------------------------------------------------------------------
// Tensor-core causal flash attention: 256 threads, 128-query CTA (8 warps x
// 16 rows), 64-key tiles double-buffered via cp.async, separate 128-row P/Q
// buffer. K/V staged once per 128 queries (2x reuse vs R9).
// ---------------------------------------------------------------------------
#define ASTR 68
#define ABUF (64 * ASTR)
#define ABUFB (ABUF * 4)
#define ATT_SMEM (6 * ABUFB)          // 2xK + 2xV + 128-row P = 104448 bytes

__global__ __launch_bounds__(256) void attn_tc(void)
{
    const int bh  = blockIdx.x;
    const int qt  = (int)gridDim.y - 1 - (int)blockIdx.y;   // heaviest first
    const int b   = bh >> 4;
    const int h   = bh & 15;
    const int q0  = qt * 128;
    const int tid = threadIdx.x;
    const int lane = tid & 31;
    const int warp = tid >> 5;          // 0..7
    const int g   = lane >> 2;
    const int t4  = lane & 3;

    extern __shared__ unsigned asmem[];
    unsigned* Ks = asmem;               // [2][64][ASTR]
    unsigned* Vs = asmem + 2 * ABUF;    // [2][64][ASTR]  Vt [d][token]
    unsigned* Ps = asmem + 4 * ABUF;    // [128][ASTR]    Q staging, then P

    const float* base = g_qkv + (size_t)b * Tc * QKV_COLS;
    const float* vtb  = g_vt + (size_t)bh * HDc * Tc;

    // Fragment bases
    const unsigned qpFrag = (unsigned)__cvta_generic_to_shared(
        &Ps[(warp * 16 + (lane & 15)) * ASTR + ((lane >> 4) << 2)]);   // Q/P A-frags
    const unsigned kFrag = (unsigned)__cvta_generic_to_shared(
        &Ks[(((lane >> 4) << 3) + (lane & 7)) * ASTR + (((lane >> 3) & 1) << 2)]);
    const unsigned vFrag = (unsigned)__cvta_generic_to_shared(
        &Vs[(((lane >> 4) << 3) + (lane & 7)) * ASTR + (((lane >> 3) & 1) << 2)]);

    // K/V staging: 64 rows, 256 threads -> 16 words each
    const int kr = tid >> 2;            // 0..63
    const int kc = (tid & 3) * 16;      // 0,16,32,48
    const unsigned kDst = (unsigned)__cvta_generic_to_shared(&Ks[kr * ASTR + kc]);
    const unsigned vDst = (unsigned)__cvta_generic_to_shared(&Vs[kr * ASTR + kc]);

    // ---- Stage Q (x0.125 exact on tf32) into Ps (128 rows) ----
    {
        const int sr = tid >> 1;            // 0..127
        const int sc = (tid & 1) * 32;
        const float* qp = base + (size_t)(q0 + sr) * QKV_COLS + h * HDc + sc;
        unsigned* dst = &Ps[sr * ASTR + sc];
#pragma unroll
        for (int i = 0; i < 32; i += 4) {
            float4 v = *(const float4*)(qp + i);
            uint4 u;
            u.x = __float_as_uint(v.x * 0.125f);
            u.y = __float_as_uint(v.y * 0.125f);
            u.z = __float_as_uint(v.z * 0.125f);
            u.w = __float_as_uint(v.w * 0.125f);
            *(uint4*)(dst + i) = u;
        }
    }
    __syncthreads();

    unsigned qf[8][4];
#pragma unroll
    for (int kb = 0; kb < 8; kb++)
        ldsm_x4(qf[kb], qpFrag + kb * 32);
    // No sync needed: each warp reads/writes only its own 16 Ps rows hereafter.

    // ---- Issue cp.async for key-tile 0 ----
    {
        const float* kp = base + (size_t)kr * QKV_COLS + Cc + h * HDc + kc;
        const float* vp = vtb + (size_t)kr * Tc + kc;
#pragma unroll
        for (int i = 0; i < 16; i += 4) {
            cp16(kDst + i * 4, kp + i);
            cp16(vDst + i * 4, vp + i);
        }
        cp_commit();
    }

    float O[8][4];
#pragma unroll
    for (int e = 0; e < 8; e++)
#pragma unroll
        for (int i = 0; i < 4; i++) O[e][i] = 0.0f;
    float m0 = -1e30f, m1 = -1e30f, l0 = 0.0f, l1 = 0.0f;

    const int r0w = warp * 16 + g;           // CTA-local query row (plus +8 pair)
    const int rowg0 = q0 + r0w;              // global query index (c0/c1)
    const int rowg1 = rowg0 + 8;             // (c2/c3)

    const int ktEnd = 2 * qt + 1;            // inclusive; kv covers [0, q0+128)

    for (int kt = 0; kt <= ktEnd; kt++) {
        const int cur = kt & 1;
        const unsigned curOff = cur * ABUFB;

        cp_wait<0>();
        __syncthreads();

        if (kt < ktEnd) {
            const int kv1 = (kt + 1) * 64;
            const unsigned nxtOff = (1 - cur) * ABUFB;
            const float* kp = base + (size_t)(kv1 + kr) * QKV_COLS + Cc + h * HDc + kc;
            const float* vp = vtb + (size_t)kr * Tc + kv1 + kc;
#pragma unroll
            for (int i = 0; i < 16; i += 4) {
                cp16(kDst + i * 4 + nxtOff, kp + i);
                cp16(vDst + i * 4 + nxtOff, vp + i);
            }
            cp_commit();
        }

        // ---- S = Q @ K^T ----
        float S[8][4];
#pragma unroll
        for (int e = 0; e < 8; e++)
#pragma unroll
            for (int i = 0; i < 4; i++) S[e][i] = 0.0f;

#pragma unroll
        for (int kb = 0; kb < 8; kb++) {
            unsigned bfr[8][2];
#pragma unroll
            for (int p = 0; p < 4; p++) {
                unsigned tmp[4];
                ldsm_x4(tmp, kFrag + curOff + p * (16 * ASTR * 4) + kb * 32);
                bfr[2 * p][0]     = tmp[0]; bfr[2 * p][1]     = tmp[1];
                bfr[2 * p + 1][0] = tmp[2]; bfr[2 * p + 1][1] = tmp[3];
            }
#pragma unroll
            for (int e = 0; e < 8; e++)
                mma_tf32(S[e], qf[kb], bfr[e]);
        }

        // ---- Causal mask (tiles overlapping/above the diagonal) ----
        if (kt >= 2 * qt) {
            const int kv0 = kt * 64;
#pragma unroll
            for (int e = 0; e < 8; e++) {
                const int jg = kv0 + e * 8 + 2 * t4;
                if (jg > rowg0)     S[e][0] = -1e30f;
                if (jg + 1 > rowg0) S[e][1] = -1e30f;
                if (jg > rowg1)     S[e][2] = -1e30f;
                if (jg + 1 > rowg1) S[e][3] = -1e30f;
            }
        }

        // ---- Online softmax ----
        float tm0 = -1e30f, tm1 = -1e30f;
#pragma unroll
        for (int e = 0; e < 8; e++) {
            tm0 = fmaxf(tm0, fmaxf(S[e][0], S[e][1]));
            tm1 = fmaxf(tm1, fmaxf(S[e][2], S[e][3]));
        }
        tm0 = fmaxf(tm0, __shfl_xor_sync(0xffffffffu, tm0, 1));
        tm0 = fmaxf(tm0, __shfl_xor_sync(0xffffffffu, tm0, 2));
        tm1 = fmaxf(tm1, __shfl_xor_sync(0xffffffffu, tm1, 1));
        tm1 = fmaxf(tm1, __shfl_xor_sync(0xffffffffu, tm1, 2));

        const float nm0 = fmaxf(m0, tm0);
        const float nm1 = fmaxf(m1, tm1);
        const float al0 = __expf(m0 - nm0);
        const float al1 = __expf(m1 - nm1);

        float ts0 = 0.0f, ts1 = 0.0f;
#pragma unroll
        for (int e = 0; e < 8; e++) {
            S[e][0] = __expf(S[e][0] - nm0);
            S[e][1] = __expf(S[e][1] - nm0);
            S[e][2] = __expf(S[e][2] - nm1);
            S[e][3] = __expf(S[e][3] - nm1);
            ts0 += S[e][0] + S[e][1];
            ts1 += S[e][2] + S[e][3];
        }
        ts0 += __shfl_xor_sync(0xffffffffu, ts0, 1);
        ts0 += __shfl_xor_sync(0xffffffffu, ts0, 2);
        ts1 += __shfl_xor_sync(0xffffffffu, ts1, 1);
        ts1 += __shfl_xor_sync(0xffffffffu, ts1, 2);

        l0 = l0 * al0 + ts0;
        l1 = l1 * al1 + ts1;
        m0 = nm0;
        m1 = nm1;

#pragma unroll
        for (int e = 0; e < 8; e++) {
            O[e][0] *= al0; O[e][1] *= al0;
            O[e][2] *= al1; O[e][3] *= al1;
        }

        // ---- Store P (tf32) into warp-private rows of Ps ----
#pragma unroll
        for (int e = 0; e < 8; e++) {
            const int c = e * 8 + 2 * t4;
            uint2 u0, u1;
            u0.x = f2tf(S[e][0]); u0.y = f2tf(S[e][1]);
            u1.x = f2tf(S[e][2]); u1.y = f2tf(S[e][3]);
            *(uint2*)(&Ps[r0w * ASTR + c])       = u0;
            *(uint2*)(&Ps[(r0w + 8) * ASTR + c]) = u1;
        }
        __syncwarp();

        // ---- O += P @ V ----
#pragma unroll
        for (int kb = 0; kb < 8; kb++) {
            unsigned af[4];
            ldsm_x4(af, qpFrag + kb * 32);
            unsigned bfr[8][2];
#pragma unroll
            for (int p = 0; p < 4; p++) {
                unsigned tmp[4];
                ldsm_x4(tmp, vFrag + curOff + p * (16 * ASTR * 4) + kb * 32);
                bfr[2 * p][0]     = tmp[0]; bfr[2 * p][1]     = tmp[1];
                bfr[2 * p + 1][0] = tmp[2]; bfr[2 * p + 1][1] = tmp[3];
            }
#pragma unroll
            for (int e = 0; e < 8; e++)
                mma_tf32(O[e], af, bfr[e]);
        }
        // top-of-loop cp_wait + __syncthreads covers K/V buffer reuse
    }

    // ---- Epilogue: normalize, round to tf32, write y ----
    const float inv0 = 1.0f / l0;
    const float inv1 = 1.0f / l1;
    float* yp0 = g_y + (size_t)(b * Tc + rowg0) * Cc + h * HDc;
    float* yp1 = g_y + (size_t)(b * Tc + rowg1) * Cc + h * HDc;
#pragma unroll
    for (int e = 0; e < 8; e++) {
        const int c = e * 8 + 2 * t4;
        float2 o0, o1;
        o0.x = __uint_as_float(f2tf(O[e][0] * inv0));
        o0.y = __uint_as_float(f2tf(O[e][1] * inv0));
        o1.x = __uint_as_float(f2tf(O[e][2] * inv1));
        o1.y = __uint_as_float(f2tf(O[e][3] * inv1));
        *(float2*)(yp0 + c) = o0;
        *(float2*)(yp1 + c) = o1;
    }
}

extern "C" void kernel_launch(void* const* d_in, const int* in_sizes, int n_in,
                              void* d_out, int out_size)
{
    const float* x      = (const float*)d_in[0];
    const float* w_attn = (const float*)d_in[1];
    const float* b_attn = (const float*)d_in[2];
    const float* w_proj = (const float*)d_in[3];
    const float* b_proj = (const float*)d_in[4];
    float* out = (float*)d_out;

    static bool attr_done = false;
    if (!attr_done) {
        cudaFuncSetAttribute(qkv_tf32, cudaFuncAttributeMaxDynamicSharedMemorySize, GEMM_SMEM);
        cudaFuncSetAttribute(proj_tf32, cudaFuncAttributeMaxDynamicSharedMemorySize, GEMM_SMEM);
        cudaFuncSetAttribute(attn_tc, cudaFuncAttributeMaxDynamicSharedMemorySize, ATT_SMEM);
        attr_done = true;
    }

    // Pre-round all inputs to tf32 (single launch)
    {
        const int total = N4_X + N4_WA + N4_WP;
        round3_kernel<<<(total + 255) / 256, 256>>>(x, w_attn, w_proj);
    }
    {
        dim3 grid(QKV_COLS / 128, M_ROWS / 128);
        qkv_tf32<<<grid, 256, GEMM_SMEM>>>(b_attn);
    }
    {
        dim3 grid(Bc * Hc, Tc / 128);
        attn_tc<<<grid, 256, ATT_SMEM>>>();
    }
    {
        dim3 grid(Cc / 128, M_ROWS / 128);
        proj_tf32<<<grid, 256, GEMM_SMEM>>>(b_proj, out);
    }
}

// round 12
// speedup vs baseline: 1.7037x; 1.7037x over previous
#include <cuda_runtime.h>
#include <cuda_fp16.h>
#include <math.h>

// Problem constants
#define Bc 2
#define Tc 2048
#define Cc 1024
#define Hc 16
#define HDc 64
#define M_ROWS (Bc * Tc)            // 4096
#define QKV_COLS (3 * Cc)           // 3072

// Scratch (device globals)
__device__ float  g_qkv[(size_t)M_ROWS * QKV_COLS];  // Q,K tf32-rounded fp32 (V region unused)
__device__ float  g_vt[(size_t)Bc * Hc * HDc * Tc];  // V transposed [b][h][d][t], tf32 fp32
__device__ __half g_y[(size_t)M_ROWS * Cc];          // attention out, fp16
__device__ __half g_xh[(size_t)M_ROWS * Cc];         // x   -> fp16
__device__ __half g_wah[(size_t)QKV_COLS * Cc];      // w_attn -> fp16
__device__ __half g_wph[(size_t)Cc * Cc];            // w_proj -> fp16

__device__ __forceinline__ unsigned f2tf(float x) {
    unsigned y;
    asm("cvt.rna.tf32.f32 %0, %1;" : "=r"(y) : "f"(x));
    return y;
}

// tf32 mma (attention, unchanged / verified)
__device__ __forceinline__ void mma_tf32(float c[4], const unsigned a[4], const unsigned b[2]) {
    asm volatile(
        "mma.sync.aligned.m16n8k8.row.col.f32.tf32.tf32.f32 "
        "{%0,%1,%2,%3}, {%4,%5,%6,%7}, {%8,%9}, {%0,%1,%2,%3};\n"
        : "+f"(c[0]), "+f"(c[1]), "+f"(c[2]), "+f"(c[3])
        : "r"(a[0]), "r"(a[1]), "r"(a[2]), "r"(a[3]), "r"(b[0]), "r"(b[1]));
}

// fp16 mma with fp32 accumulate (GEMMs)
__device__ __forceinline__ void mma_f16(float c[4], const unsigned a[4], const unsigned b[2]) {
    asm volatile(
        "mma.sync.aligned.m16n8k16.row.col.f32.f16.f16.f32 "
        "{%0,%1,%2,%3}, {%4,%5,%6,%7}, {%8,%9}, {%0,%1,%2,%3};\n"
        : "+f"(c[0]), "+f"(c[1]), "+f"(c[2]), "+f"(c[3])
        : "r"(a[0]), "r"(a[1]), "r"(a[2]), "r"(a[3]), "r"(b[0]), "r"(b[1]));
}

__device__ __forceinline__ void ldsm_x4(unsigned r[4], unsigned addr) {
    asm volatile("ldmatrix.sync.aligned.m8n8.x4.shared.b16 {%0,%1,%2,%3}, [%4];"
        : "=r"(r[0]), "=r"(r[1]), "=r"(r[2]), "=r"(r[3]) : "r"(addr));
}

__device__ __forceinline__ void cp16(unsigned dst, const void* src) {
    asm volatile("cp.async.cg.shared.global [%0], [%1], 16;" :: "r"(dst), "l"(src));
}
__device__ __forceinline__ void cp_commit() { asm volatile("cp.async.commit_group;"); }
template <int N> __device__ __forceinline__ void cp_wait() {
    asm volatile("cp.async.wait_group %0;" :: "n"(N));
}

// ---------------------------------------------------------------------------
// Fused conversion of x, w_attn, w_proj to fp16 (one launch)
// ---------------------------------------------------------------------------
#define N4_X  ((M_ROWS * Cc) / 4)
#define N4_WA ((QKV_COLS * Cc) / 4)
#define N4_WP ((Cc * Cc) / 4)

__global__ void conv3_kernel(const float* __restrict__ x,
                             const float* __restrict__ wa,
                             const float* __restrict__ wp)
{
    int i = blockIdx.x * blockDim.x + threadIdx.x;
    const float4* src;
    __half* dst;
    int j = i;
    if (j < N4_X) {
        src = (const float4*)x;  dst = g_xh;
    } else if ((j -= N4_X) < N4_WA) {
        src = (const float4*)wa; dst = g_wah;
    } else if ((j -= N4_WA) < N4_WP) {
        src = (const float4*)wp; dst = g_wph;
    } else {
        return;
    }
    float4 v = src[j];
    __half2 h0 = __floats2half2_rn(v.x, v.y);
    __half2 h1 = __floats2half2_rn(v.z, v.w);
    *(__half2*)(dst + (size_t)j * 4)     = h0;
    *(__half2*)(dst + (size_t)j * 4 + 2) = h1;
}

// ---------------------------------------------------------------------------
// FP16 GEMM: C = A @ W^T + bias. 128x128 tile, 8 warps, 64x32 warp tile,
// KT=32 halves (64B/row/stage, same bytes as R9 tf32 KT=16), 4-stage ring.
// Byte-level smem layout identical to verified R9 tf32 path.
// ---------------------------------------------------------------------------
#define SROWH 40                      // halves: 32 data... (64B data + 16B pad = 80B)
#define STGH (128 * SROWH)            // halves per matrix per stage
#define STGB (STGH * 2)               // bytes per matrix per stage = 10240
#define NSTG 4
#define GEMM_SMEM (2 * NSTG * STGB)   // 81920 bytes
#define KTH 32                        // k-halves per stage

template <bool TF32_OUT, bool V_SPLIT>
__device__ __forceinline__ void gemm_f16_body(
    const __half* __restrict__ A, const __half* __restrict__ Wt,
    const float* __restrict__ bias, float* __restrict__ C,
    int N, int K)
{
    extern __shared__ __half hsmem[];
    __half* As = hsmem;
    __half* Bs = hsmem + NSTG * STGH;

    const int tid  = threadIdx.x;
    const int lane = tid & 31;
    const int g    = lane >> 2;
    const int t4   = lane & 3;
    const int warp = tid >> 5;          // 0..7
    const int wm   = (warp >> 2) * 64;
    const int wn   = (warp & 3) * 32;
    const int brow = blockIdx.y * 128;
    const int bcol = blockIdx.x * 128;

    // Staging: thread -> row lr, half-offset lkh (0 or 16); 2 cp16 per matrix
    const int lr  = tid >> 1;
    const int lkh = (tid & 1) * 16;
    const __half* Asrc = A  + (size_t)(brow + lr) * K + lkh;
    const __half* Bsrc = Wt + (size_t)(bcol + lr) * K + lkh;
    const unsigned aDst = (unsigned)__cvta_generic_to_shared(&As[lr * SROWH + lkh]);
    const unsigned bDst = (unsigned)__cvta_generic_to_shared(&Bs[lr * SROWH + lkh]);

    // Fragment bases (byte-identical pattern to verified tf32 path)
    const unsigned aFrag = (unsigned)__cvta_generic_to_shared(
        &As[(wm + (lane & 15)) * SROWH + ((lane >> 4) << 3)]);
    const unsigned bFrag = (unsigned)__cvta_generic_to_shared(
        &Bs[(wn + ((lane >> 4) << 3) + (lane & 7)) * SROWH + (((lane >> 3) & 1) << 3)]);

    float acc[4][4][4];
#pragma unroll
    for (int f = 0; f < 4; f++)
#pragma unroll
        for (int e = 0; e < 4; e++)
#pragma unroll
            for (int i = 0; i < 4; i++) acc[f][e][i] = 0.0f;

    const int NT = K / KTH;             // 32

#pragma unroll
    for (int s = 0; s < NSTG - 1; s++) {
        const unsigned off = s * STGB;
        const __half* Ap = Asrc + s * KTH;
        const __half* Bp = Bsrc + s * KTH;
        cp16(aDst + off,      Ap);
        cp16(aDst + off + 16, Ap + 8);
        cp16(bDst + off,      Bp);
        cp16(bDst + off + 16, Bp + 8);
        cp_commit();
    }

    for (int t = 0; t < NT; t++) {
        cp_wait<NSTG - 2>();
        __syncthreads();

        if (t + NSTG - 1 < NT) {
            const unsigned off = ((t + NSTG - 1) & (NSTG - 1)) * STGB;
            const __half* Ap = Asrc + (size_t)(t + NSTG - 1) * KTH;
            const __half* Bp = Bsrc + (size_t)(t + NSTG - 1) * KTH;
            cp16(aDst + off,      Ap);
            cp16(aDst + off + 16, Ap + 8);
            cp16(bDst + off,      Bp);
            cp16(bDst + off + 16, Bp + 8);
            cp_commit();
        }

        const unsigned curOff = (t & (NSTG - 1)) * STGB;
#pragma unroll
        for (int kb = 0; kb < 2; kb++) {     // 2 x k16 per stage
            unsigned af[4][4], bf[4][2];
#pragma unroll
            for (int f = 0; f < 4; f++)
                ldsm_x4(af[f], aFrag + curOff + f * (16 * SROWH * 2) + kb * 32);
#pragma unroll
            for (int p = 0; p < 2; p++) {
                unsigned tmp[4];
                ldsm_x4(tmp, bFrag + curOff + p * (16 * SROWH * 2) + kb * 32);
                bf[2 * p][0]     = tmp[0]; bf[2 * p][1]     = tmp[1];
                bf[2 * p + 1][0] = tmp[2]; bf[2 * p + 1][1] = tmp[3];
            }
#pragma unroll
            for (int f = 0; f < 4; f++)
#pragma unroll
                for (int e = 0; e < 4; e++)
                    mma_f16(acc[f][e], af[f], bf[e]);
        }
    }

    // Epilogue
    if (V_SPLIT && bcol >= 2 * Cc) {
        // V block: write transposed fp32 (tf32-rounded) into g_vt[b][h][d][t]
#pragma unroll
        for (int f = 0; f < 4; f++) {
            const int r0 = brow + wm + f * 16 + g;
            const int bb = r0 >> 11;
            const int tt = r0 & (Tc - 1);
#pragma unroll
            for (int e = 0; e < 4; e++) {
                const int c = bcol + wn + e * 8 + t4 * 2;
                const int local = c - 2 * Cc;
                const int hh = local >> 6;
                const int dd = local & 63;
                float v0 = acc[f][e][0] + bias[c];
                float v1 = acc[f][e][1] + bias[c + 1];
                float v2 = acc[f][e][2] + bias[c];
                float v3 = acc[f][e][3] + bias[c + 1];
                v0 = __uint_as_float(f2tf(v0)); v1 = __uint_as_float(f2tf(v1));
                v2 = __uint_as_float(f2tf(v2)); v3 = __uint_as_float(f2tf(v3));
                float* vb = g_vt + ((size_t)(bb * Hc + hh) * HDc + dd) * Tc;
                vb[tt]          = v0;
                vb[Tc + tt]     = v1;
                vb[tt + 8]      = v2;
                vb[Tc + tt + 8] = v3;
            }
        }
        return;
    }

#pragma unroll
    for (int f = 0; f < 4; f++) {
        const int r0 = brow + wm + f * 16 + g;
#pragma unroll
        for (int e = 0; e < 4; e++) {
            const int c = bcol + wn + e * 8 + t4 * 2;
            const float b0v = bias[c];
            const float b1v = bias[c + 1];
            float2 o0, o1;
            o0.x = acc[f][e][0] + b0v;  o0.y = acc[f][e][1] + b1v;
            o1.x = acc[f][e][2] + b0v;  o1.y = acc[f][e][3] + b1v;
            if (TF32_OUT) {
                o0.x = __uint_as_float(f2tf(o0.x)); o0.y = __uint_as_float(f2tf(o0.y));
                o1.x = __uint_as_float(f2tf(o1.x)); o1.y = __uint_as_float(f2tf(o1.y));
            }
            *(float2*)(&C[(size_t)r0 * N + c]) = o0;
            *(float2*)(&C[(size_t)(r0 + 8) * N + c]) = o1;
        }
    }
}

__global__ __launch_bounds__(256, 2) void qkv_f16(const float* __restrict__ b)
{
    gemm_f16_body<true, true>(g_xh, g_wah, b, g_qkv, QKV_COLS, Cc);
}

// proj A = g_y (fp16, written by attention); no staging conversion needed
__global__ __launch_bounds__(256, 2) void proj_f16(const float* __restrict__ b,
                                                   float* __restrict__ out)
{
    gemm_f16_body<false, false>(g_y, g_wph, b, out, Cc, Cc);
}

// ---------------------------------------------------------------------------
// Tensor-core causal flash attention — R9 structure VERBATIM (tf32, 128 thr,
// 64-query CTA, double-buffered K/Vt via cp.async, ldmatrix frags).
// Only change: epilogue writes g_y as fp16.
// ---------------------------------------------------------------------------
#define ASTR 68
#define ABUF (64 * ASTR)
#define ABUFB (ABUF * 4)
#define ATT_SMEM (4 * ABUFB)         // 69632 bytes

__global__ __launch_bounds__(128) void attn_tc(void)
{
    const int bh  = blockIdx.x;
    const int qt  = blockIdx.y;
    const int b   = bh >> 4;
    const int h   = bh & 15;
    const int q0  = qt * 64;
    const int tid = threadIdx.x;
    const int lane = tid & 31;
    const int warp = tid >> 5;
    const int g   = lane >> 2;
    const int t4  = lane & 3;

    extern __shared__ unsigned asmem[];
    unsigned* Ks = asmem;
    unsigned* Vs = asmem + 2 * ABUF;

    const float* base = g_qkv + (size_t)b * Tc * QKV_COLS;
    const float* vtb  = g_vt + (size_t)bh * HDc * Tc;

    const unsigned qpFrag = (unsigned)__cvta_generic_to_shared(
        &Ks[(warp * 16 + (lane & 15)) * ASTR + ((lane >> 4) << 2)]);
    const unsigned kFrag = (unsigned)__cvta_generic_to_shared(
        &Ks[(((lane >> 4) << 3) + (lane & 7)) * ASTR + (((lane >> 3) & 1) << 2)]);
    const unsigned vFrag = (unsigned)__cvta_generic_to_shared(
        &Vs[(((lane >> 4) << 3) + (lane & 7)) * ASTR + (((lane >> 3) & 1) << 2)]);

    const int sr = tid >> 1;
    const int sc = (tid & 1) * 32;
    const unsigned kDst = (unsigned)__cvta_generic_to_shared(&Ks[sr * ASTR + sc]);
    const unsigned vDst = (unsigned)__cvta_generic_to_shared(&Vs[sr * ASTR + sc]);

    // ---- Stage Q (×0.125 exact on tf32) into Ks[0], read qf ----
    {
        const float* qp = base + (size_t)(q0 + sr) * QKV_COLS + h * HDc + sc;
        unsigned* dst = &Ks[sr * ASTR + sc];
#pragma unroll
        for (int i = 0; i < 32; i += 4) {
            float4 v = *(const float4*)(qp + i);
            uint4 u;
            u.x = __float_as_uint(v.x * 0.125f);
            u.y = __float_as_uint(v.y * 0.125f);
            u.z = __float_as_uint(v.z * 0.125f);
            u.w = __float_as_uint(v.w * 0.125f);
            *(uint4*)(dst + i) = u;
        }
    }
    __syncthreads();

    unsigned qf[8][4];
#pragma unroll
    for (int kb = 0; kb < 8; kb++)
        ldsm_x4(qf[kb], qpFrag + kb * 32);
    __syncthreads();

    // ---- Issue cp.async for tile 0 ----
    {
        const float* kp = base + (size_t)sr * QKV_COLS + Cc + h * HDc + sc;
        const float* vp = vtb + (size_t)sr * Tc + sc;
#pragma unroll
        for (int i = 0; i < 32; i += 4) {
            cp16(kDst + i * 4, kp + i);
            cp16(vDst + i * 4, vp + i);
        }
        cp_commit();
    }

    float O[8][4];
#pragma unroll
    for (int e = 0; e < 8; e++)
#pragma unroll
        for (int i = 0; i < 4; i++) O[e][i] = 0.0f;
    float m0 = -1e30f, m1 = -1e30f, l0 = 0.0f, l1 = 0.0f;

    const int r0w = warp * 16 + g;

    for (int kt = 0; kt <= qt; kt++) {
        const int cur = kt & 1;
        const unsigned curOff = cur * ABUFB;

        cp_wait<0>();
        __syncthreads();

        if (kt < qt) {
            const int kv1 = (kt + 1) * 64;
            const unsigned nxtOff = (1 - cur) * ABUFB;
            const float* kp = base + (size_t)(kv1 + sr) * QKV_COLS + Cc + h * HDc + sc;
            const float* vp = vtb + (size_t)sr * Tc + kv1 + sc;
#pragma unroll
            for (int i = 0; i < 32; i += 4) {
                cp16(kDst + nxtOff + i * 4, kp + i);
                cp16(vDst + nxtOff + i * 4, vp + i);
            }
            cp_commit();
        }

        // ---- S = Q @ K^T ----
        float S[8][4];
#pragma unroll
        for (int e = 0; e < 8; e++)
#pragma unroll
            for (int i = 0; i < 4; i++) S[e][i] = 0.0f;

#pragma unroll
        for (int kb = 0; kb < 8; kb++) {
            unsigned bfr[8][2];
#pragma unroll
            for (int p = 0; p < 4; p++) {
                unsigned tmp[4];
                ldsm_x4(tmp, kFrag + curOff + p * (16 * ASTR * 4) + kb * 32);
                bfr[2 * p][0]     = tmp[0]; bfr[2 * p][1]     = tmp[1];
                bfr[2 * p + 1][0] = tmp[2]; bfr[2 * p + 1][1] = tmp[3];
            }
#pragma unroll
            for (int e = 0; e < 8; e++)
                mma_tf32(S[e], qf[kb], bfr[e]);
        }

        // ---- Causal mask (diagonal tile) ----
        if (kt == qt) {
#pragma unroll
            for (int e = 0; e < 8; e++) {
                const int j = e * 8 + 2 * t4;
                if (j > r0w)         S[e][0] = -1e30f;
                if (j + 1 > r0w)     S[e][1] = -1e30f;
                if (j > r0w + 8)     S[e][2] = -1e30f;
                if (j + 1 > r0w + 8) S[e][3] = -1e30f;
            }
        }

        // ---- Online softmax ----
        float tm0 = -1e30f, tm1 = -1e30f;
#pragma unroll
        for (int e = 0; e < 8; e++) {
            tm0 = fmaxf(tm0, fmaxf(S[e][0], S[e][1]));
            tm1 = fmaxf(tm1, fmaxf(S[e][2], S[e][3]));
        }
        tm0 = fmaxf(tm0, __shfl_xor_sync(0xffffffffu, tm0, 1));
        tm0 = fmaxf(tm0, __shfl_xor_sync(0xffffffffu, tm0, 2));
        tm1 = fmaxf(tm1, __shfl_xor_sync(0xffffffffu, tm1, 1));
        tm1 = fmaxf(tm1, __shfl_xor_sync(0xffffffffu, tm1, 2));

        const float nm0 = fmaxf(m0, tm0);
        const float nm1 = fmaxf(m1, tm1);
        const float al0 = __expf(m0 - nm0);
        const float al1 = __expf(m1 - nm1);

        float ts0 = 0.0f, ts1 = 0.0f;
#pragma unroll
        for (int e = 0; e < 8; e++) {
            S[e][0] = __expf(S[e][0] - nm0);
            S[e][1] = __expf(S[e][1] - nm0);
            S[e][2] = __expf(S[e][2] - nm1);
            S[e][3] = __expf(S[e][3] - nm1);
            ts0 += S[e][0] + S[e][1];
            ts1 += S[e][2] + S[e][3];
        }
        ts0 += __shfl_xor_sync(0xffffffffu, ts0, 1);
        ts0 += __shfl_xor_sync(0xffffffffu, ts0, 2);
        ts1 += __shfl_xor_sync(0xffffffffu, ts1, 1);
        ts1 += __shfl_xor_sync(0xffffffffu, ts1, 2);

        l0 = l0 * al0 + ts0;
        l1 = l1 * al1 + ts1;
        m0 = nm0;
        m1 = nm1;

#pragma unroll
        for (int e = 0; e < 8; e++) {
            O[e][0] *= al0; O[e][1] *= al0;
            O[e][2] *= al1; O[e][3] *= al1;
        }

        __syncthreads();

        // ---- Store P (tf32) into warp-private rows of Ks[cur] ----
#pragma unroll
        for (int e = 0; e < 8; e++) {
            const int c = e * 8 + 2 * t4;
            uint2 u0, u1;
            u0.x = f2tf(S[e][0]); u0.y = f2tf(S[e][1]);
            u1.x = f2tf(S[e][2]); u1.y = f2tf(S[e][3]);
            *(uint2*)(&Ks[cur * ABUF + r0w * ASTR + c])       = u0;
            *(uint2*)(&Ks[cur * ABUF + (r0w + 8) * ASTR + c]) = u1;
        }
        __syncwarp();

        // ---- O += P @ V ----
#pragma unroll
        for (int kb = 0; kb < 8; kb++) {
            unsigned af[4];
            ldsm_x4(af, qpFrag + curOff + kb * 32);
            unsigned bfr[8][2];
#pragma unroll
            for (int p = 0; p < 4; p++) {
                unsigned tmp[4];
                ldsm_x4(tmp, vFrag + curOff + p * (16 * ASTR * 4) + kb * 32);
                bfr[2 * p][0]     = tmp[0]; bfr[2 * p][1]     = tmp[1];
                bfr[2 * p + 1][0] = tmp[2]; bfr[2 * p + 1][1] = tmp[3];
            }
#pragma unroll
            for (int e = 0; e < 8; e++)
                mma_tf32(O[e], af, bfr[e]);
        }
    }

    // ---- Epilogue: normalize, write y as fp16 (feeds fp16 proj GEMM) ----
    const float inv0 = 1.0f / l0;
    const float inv1 = 1.0f / l1;
    const int gr = q0 + r0w;
    __half* yp0 = g_y + (size_t)(b * Tc + gr) * Cc + h * HDc;
    __half* yp1 = g_y + (size_t)(b * Tc + gr + 8) * Cc + h * HDc;
#pragma unroll
    for (int e = 0; e < 8; e++) {
        const int c = e * 8 + 2 * t4;
        *(__half2*)(yp0 + c) = __floats2half2_rn(O[e][0] * inv0, O[e][1] * inv0);
        *(__half2*)(yp1 + c) = __floats2half2_rn(O[e][2] * inv1, O[e][3] * inv1);
    }
}

extern "C" void kernel_launch(void* const* d_in, const int* in_sizes, int n_in,
                              void* d_out, int out_size)
{
    const float* x      = (const float*)d_in[0];
    const float* w_attn = (const float*)d_in[1];
    const float* b_attn = (const float*)d_in[2];
    const float* w_proj = (const float*)d_in[3];
    const float* b_proj = (const float*)d_in[4];
    float* out = (float*)d_out;

    static bool attr_done = false;
    if (!attr_done) {
        cudaFuncSetAttribute(qkv_f16, cudaFuncAttributeMaxDynamicSharedMemorySize, GEMM_SMEM);
        cudaFuncSetAttribute(proj_f16, cudaFuncAttributeMaxDynamicSharedMemorySize, GEMM_SMEM);
        cudaFuncSetAttribute(attn_tc, cudaFuncAttributeMaxDynamicSharedMemorySize, ATT_SMEM);
        attr_done = true;
    }

    // Convert inputs to fp16 (single launch)
    {
        const int total = N4_X + N4_WA + N4_WP;
        conv3_kernel<<<(total + 255) / 256, 256>>>(x, w_attn, w_proj);
    }
    {
        dim3 grid(QKV_COLS / 128, M_ROWS / 128);
        qkv_f16<<<grid, 256, GEMM_SMEM>>>(b_attn);
    }
    {
        dim3 grid(Bc * Hc, Tc / 64);
        attn_tc<<<grid, 128, ATT_SMEM>>>();
    }
    {
        dim3 grid(Cc / 128, M_ROWS / 128);
        proj_f16<<<grid, 256, GEMM_SMEM>>>(b_proj, out);
    }
}

// round 14
// speedup vs baseline: 2.5981x; 1.5250x over previous
#include <cuda_runtime.h>
#include <cuda_fp16.h>
#include <math.h>

// Problem constants
#define Bc 2
#define Tc 2048
#define Cc 1024
#define Hc 16
#define HDc 64
#define M_ROWS (Bc * Tc)            // 4096
#define QKV_COLS (3 * Cc)           // 3072

// Scratch (device globals)
__device__ __half g_qkvh[(size_t)M_ROWS * QKV_COLS]; // Q(x0.125),K fp16 (V region unused)
__device__ __half g_vth[(size_t)Bc * Hc * HDc * Tc]; // V transposed [b][h][d][t], fp16
__device__ __half g_y[(size_t)M_ROWS * Cc];          // attention out, fp16
__device__ __half g_xh[(size_t)M_ROWS * Cc];         // x   -> fp16
__device__ __half g_wah[(size_t)QKV_COLS * Cc];      // w_attn -> fp16
__device__ __half g_wph[(size_t)Cc * Cc];            // w_proj -> fp16

// fp16 mma with fp32 accumulate
__device__ __forceinline__ void mma_f16(float c[4], const unsigned a[4], const unsigned b[2]) {
    asm volatile(
        "mma.sync.aligned.m16n8k16.row.col.f32.f16.f16.f32 "
        "{%0,%1,%2,%3}, {%4,%5,%6,%7}, {%8,%9}, {%0,%1,%2,%3};\n"
        : "+f"(c[0]), "+f"(c[1]), "+f"(c[2]), "+f"(c[3])
        : "r"(a[0]), "r"(a[1]), "r"(a[2]), "r"(a[3]), "r"(b[0]), "r"(b[1]));
}

__device__ __forceinline__ void ldsm_x4(unsigned r[4], unsigned addr) {
    asm volatile("ldmatrix.sync.aligned.m8n8.x4.shared.b16 {%0,%1,%2,%3}, [%4];"
        : "=r"(r[0]), "=r"(r[1]), "=r"(r[2]), "=r"(r[3]) : "r"(addr));
}

__device__ __forceinline__ void cp16(unsigned dst, const void* src) {
    asm volatile("cp.async.cg.shared.global [%0], [%1], 16;" :: "r"(dst), "l"(src));
}
__device__ __forceinline__ void cp_commit() { asm volatile("cp.async.commit_group;"); }
template <int N> __device__ __forceinline__ void cp_wait() {
    asm volatile("cp.async.wait_group %0;" :: "n"(N));
}

// ---------------------------------------------------------------------------
// Fused conversion of x, w_attn, w_proj to fp16 (one launch)
// ---------------------------------------------------------------------------
#define N4_X  ((M_ROWS * Cc) / 4)
#define N4_WA ((QKV_COLS * Cc) / 4)
#define N4_WP ((Cc * Cc) / 4)

__global__ void conv3_kernel(const float* __restrict__ x,
                             const float* __restrict__ wa,
                             const float* __restrict__ wp)
{
    int i = blockIdx.x * blockDim.x + threadIdx.x;
    const float4* src;
    __half* dst;
    int j = i;
    if (j < N4_X) {
        src = (const float4*)x;  dst = g_xh;
    } else if ((j -= N4_X) < N4_WA) {
        src = (const float4*)wa; dst = g_wah;
    } else if ((j -= N4_WA) < N4_WP) {
        src = (const float4*)wp; dst = g_wph;
    } else {
        return;
    }
    float4 v = src[j];
    __half2 h0 = __floats2half2_rn(v.x, v.y);
    __half2 h1 = __floats2half2_rn(v.z, v.w);
    *(__half2*)(dst + (size_t)j * 4)     = h0;
    *(__half2*)(dst + (size_t)j * 4 + 2) = h1;
}

// ---------------------------------------------------------------------------
// FP16 GEMM: 128x128 tile, 8 warps, 64x32 warp tile, 4-stage cp.async ring,
// ldmatrix x4 fragment loads (verified R12).
// OUT_MODE 0: fp32 C + bias.  OUT_MODE 1 (qkv): Q(x0.125)/K -> g_qkvh fp16,
//   V -> g_vth fp16 transposed.
// ---------------------------------------------------------------------------
#define SROWH 40
#define STGH (128 * SROWH)
#define STGB (STGH * 2)
#define NSTG 4
#define GEMM_SMEM (2 * NSTG * STGB)   // 81920 bytes
#define KTH 32

template <int OUT_MODE>
__device__ __forceinline__ void gemm_f16_body(
    const __half* __restrict__ A, const __half* __restrict__ Wt,
    const float* __restrict__ bias, float* __restrict__ C,
    int N, int K)
{
    extern __shared__ __half hsmem[];
    __half* As = hsmem;
    __half* Bs = hsmem + NSTG * STGH;

    const int tid  = threadIdx.x;
    const int lane = tid & 31;
    const int g    = lane >> 2;
    const int t4   = lane & 3;
    const int warp = tid >> 5;
    const int wm   = (warp >> 2) * 64;
    const int wn   = (warp & 3) * 32;
    const int brow = blockIdx.y * 128;
    const int bcol = blockIdx.x * 128;

    const int lr  = tid >> 1;
    const int lkh = (tid & 1) * 16;
    const __half* Asrc = A  + (size_t)(brow + lr) * K + lkh;
    const __half* Bsrc = Wt + (size_t)(bcol + lr) * K + lkh;
    const unsigned aDst = (unsigned)__cvta_generic_to_shared(&As[lr * SROWH + lkh]);
    const unsigned bDst = (unsigned)__cvta_generic_to_shared(&Bs[lr * SROWH + lkh]);

    const unsigned aFrag = (unsigned)__cvta_generic_to_shared(
        &As[(wm + (lane & 15)) * SROWH + ((lane >> 4) << 3)]);
    const unsigned bFrag = (unsigned)__cvta_generic_to_shared(
        &Bs[(wn + ((lane >> 4) << 3) + (lane & 7)) * SROWH + (((lane >> 3) & 1) << 3)]);

    float acc[4][4][4];
#pragma unroll
    for (int f = 0; f < 4; f++)
#pragma unroll
        for (int e = 0; e < 4; e++)
#pragma unroll
            for (int i = 0; i < 4; i++) acc[f][e][i] = 0.0f;

    const int NT = K / KTH;

#pragma unroll
    for (int s = 0; s < NSTG - 1; s++) {
        const unsigned off = s * STGB;
        const __half* Ap = Asrc + s * KTH;
        const __half* Bp = Bsrc + s * KTH;
        cp16(aDst + off,      Ap);
        cp16(aDst + off + 16, Ap + 8);
        cp16(bDst + off,      Bp);
        cp16(bDst + off + 16, Bp + 8);
        cp_commit();
    }

    for (int t = 0; t < NT; t++) {
        cp_wait<NSTG - 2>();
        __syncthreads();

        if (t + NSTG - 1 < NT) {
            const unsigned off = ((t + NSTG - 1) & (NSTG - 1)) * STGB;
            const __half* Ap = Asrc + (size_t)(t + NSTG - 1) * KTH;
            const __half* Bp = Bsrc + (size_t)(t + NSTG - 1) * KTH;
            cp16(aDst + off,      Ap);
            cp16(aDst + off + 16, Ap + 8);
            cp16(bDst + off,      Bp);
            cp16(bDst + off + 16, Bp + 8);
            cp_commit();
        }

        const unsigned curOff = (t & (NSTG - 1)) * STGB;
#pragma unroll
        for (int kb = 0; kb < 2; kb++) {
            unsigned af[4][4], bf[4][2];
#pragma unroll
            for (int f = 0; f < 4; f++)
                ldsm_x4(af[f], aFrag + curOff + f * (16 * SROWH * 2) + kb * 32);
#pragma unroll
            for (int p = 0; p < 2; p++) {
                unsigned tmp[4];
                ldsm_x4(tmp, bFrag + curOff + p * (16 * SROWH * 2) + kb * 32);
                bf[2 * p][0]     = tmp[0]; bf[2 * p][1]     = tmp[1];
                bf[2 * p + 1][0] = tmp[2]; bf[2 * p + 1][1] = tmp[3];
            }
#pragma unroll
            for (int f = 0; f < 4; f++)
#pragma unroll
                for (int e = 0; e < 4; e++)
                    mma_f16(acc[f][e], af[f], bf[e]);
        }
    }

    // Epilogue
    if (OUT_MODE == 1) {
        if (bcol >= 2 * Cc) {
            // V block -> g_vth transposed fp16
#pragma unroll
            for (int f = 0; f < 4; f++) {
                const int r0 = brow + wm + f * 16 + g;
                const int bb = r0 >> 11;
                const int tt = r0 & (Tc - 1);
#pragma unroll
                for (int e = 0; e < 4; e++) {
                    const int c = bcol + wn + e * 8 + t4 * 2;
                    const int local = c - 2 * Cc;
                    const int hh = local >> 6;
                    const int dd = local & 63;
                    __half* vb = g_vth + ((size_t)(bb * Hc + hh) * HDc + dd) * Tc;
                    vb[tt]          = __float2half_rn(acc[f][e][0] + bias[c]);
                    vb[Tc + tt]     = __float2half_rn(acc[f][e][1] + bias[c + 1]);
                    vb[tt + 8]      = __float2half_rn(acc[f][e][2] + bias[c]);
                    vb[Tc + tt + 8] = __float2half_rn(acc[f][e][3] + bias[c + 1]);
                }
            }
        } else {
            // Q (x0.125) / K block -> g_qkvh fp16
            const float qscale = (bcol < Cc) ? 0.125f : 1.0f;
#pragma unroll
            for (int f = 0; f < 4; f++) {
                const int r0 = brow + wm + f * 16 + g;
#pragma unroll
                for (int e = 0; e < 4; e++) {
                    const int c = bcol + wn + e * 8 + t4 * 2;
                    const float b0v = bias[c];
                    const float b1v = bias[c + 1];
                    __half* p0 = g_qkvh + (size_t)r0 * QKV_COLS + c;
                    __half* p1 = g_qkvh + (size_t)(r0 + 8) * QKV_COLS + c;
                    *(__half2*)p0 = __floats2half2_rn((acc[f][e][0] + b0v) * qscale,
                                                      (acc[f][e][1] + b1v) * qscale);
                    *(__half2*)p1 = __floats2half2_rn((acc[f][e][2] + b0v) * qscale,
                                                      (acc[f][e][3] + b1v) * qscale);
                }
            }
        }
        return;
    }

#pragma unroll
    for (int f = 0; f < 4; f++) {
        const int r0 = brow + wm + f * 16 + g;
#pragma unroll
        for (int e = 0; e < 4; e++) {
            const int c = bcol + wn + e * 8 + t4 * 2;
            float2 o0, o1;
            o0.x = acc[f][e][0] + bias[c];      o0.y = acc[f][e][1] + bias[c + 1];
            o1.x = acc[f][e][2] + bias[c];      o1.y = acc[f][e][3] + bias[c + 1];
            *(float2*)(&C[(size_t)r0 * N + c]) = o0;
            *(float2*)(&C[(size_t)(r0 + 8) * N + c]) = o1;
        }
    }
}

__global__ __launch_bounds__(256, 2) void qkv_f16(const float* __restrict__ b)
{
    gemm_f16_body<1>(g_xh, g_wah, b, (float*)0, QKV_COLS, Cc);
}

__global__ __launch_bounds__(256, 2) void proj_f16(const float* __restrict__ b,
                                                   float* __restrict__ out)
{
    gemm_f16_body<0>(g_y, g_wph, b, out, Cc, Cc);
}

// ---------------------------------------------------------------------------
// FP16 tensor-core causal flash attention. 128 thr, 64-query CTA.
// K/V tiles 64x64 halves (stride 72), double-buffered cp.async.
// All mma m16n8k16 fp16. P stored fp16 in K buffer.
// ---------------------------------------------------------------------------
#define ASTRH 72                     // halves per row (144B; 36w stride, cf-free)
#define ABUFH (64 * ASTRH)           // halves per buffer
#define ABUFB2 (ABUFH * 2)           // bytes per buffer = 9216
#define ATT_SMEM (4 * ABUFB2)        // 2xK + 2xV = 36864 bytes

__global__ __launch_bounds__(128) void attn_tc(void)
{
    const int bh  = blockIdx.x;
    const int qt  = blockIdx.y;
    const int b   = bh >> 4;
    const int h   = bh & 15;
    const int q0  = qt * 64;
    const int tid = threadIdx.x;
    const int lane = tid & 31;
    const int warp = tid >> 5;
    const int g   = lane >> 2;
    const int t4  = lane & 3;

    extern __shared__ __half ahsmem[];
    __half* Ks = ahsmem;               // [2][64][ASTRH]  K tile (later P)
    __half* Vs = ahsmem + 2 * ABUFH;   // [2][64][ASTRH]  Vt tile [d][token]

    const __half* base = g_qkvh + (size_t)b * Tc * QKV_COLS;
    const __half* vtb  = g_vth + (size_t)bh * HDc * Tc;

    // Fragment bases (buffer 0; +cur*ABUFB2)
    const unsigned qpFrag = (unsigned)__cvta_generic_to_shared(
        &Ks[(warp * 16 + (lane & 15)) * ASTRH + ((lane >> 4) << 3)]);  // Q/P A-frags
    const unsigned kFrag = (unsigned)__cvta_generic_to_shared(
        &Ks[(((lane >> 4) << 3) + (lane & 7)) * ASTRH + (((lane >> 3) & 1) << 3)]);
    const unsigned vFrag = (unsigned)__cvta_generic_to_shared(
        &Vs[(((lane >> 4) << 3) + (lane & 7)) * ASTRH + (((lane >> 3) & 1) << 3)]);

    // Staging mapping: 64 rows x 128B; thread -> row sr, 64B half-offset sc
    const int sr = tid >> 1;
    const int sc = (tid & 1) * 32;
    const unsigned kDst = (unsigned)__cvta_generic_to_shared(&Ks[sr * ASTRH + sc]);
    const unsigned vDst = (unsigned)__cvta_generic_to_shared(&Vs[sr * ASTRH + sc]);

    // ---- Stage Q (already x0.125, fp16) into Ks[0] via cp.async ----
    {
        const __half* qp = base + (size_t)(q0 + sr) * QKV_COLS + h * HDc + sc;
        cp16(kDst,      qp);
        cp16(kDst + 16, qp + 8);
        cp16(kDst + 32, qp + 16);
        cp16(kDst + 48, qp + 24);
        cp_commit();
    }
    cp_wait<0>();
    __syncthreads();

    unsigned qf[4][4];
#pragma unroll
    for (int kb = 0; kb < 4; kb++)
        ldsm_x4(qf[kb], qpFrag + kb * 32);
    __syncthreads();   // all warps hold qf before K tile 0 overwrites Ks[0]

    // ---- Issue cp.async for tile 0 ----
    {
        const __half* kp = base + (size_t)sr * QKV_COLS + Cc + h * HDc + sc;
        const __half* vp = vtb + (size_t)sr * Tc + sc;
        cp16(kDst,      kp);  cp16(kDst + 16, kp + 8);
        cp16(kDst + 32, kp + 16); cp16(kDst + 48, kp + 24);
        cp16(vDst,      vp);  cp16(vDst + 16, vp + 8);
        cp16(vDst + 32, vp + 16); cp16(vDst + 48, vp + 24);
        cp_commit();
    }

    float O[8][4];
#pragma unroll
    for (int e = 0; e < 8; e++)
#pragma unroll
        for (int i = 0; i < 4; i++) O[e][i] = 0.0f;
    float m0 = -1e30f, m1 = -1e30f, l0 = 0.0f, l1 = 0.0f;

    const int r0w = warp * 16 + g;

    for (int kt = 0; kt <= qt; kt++) {
        const int cur = kt & 1;
        const unsigned curOff = cur * ABUFB2;

        cp_wait<0>();
        __syncthreads();

        if (kt < qt) {
            const int kv1 = (kt + 1) * 64;
            const unsigned nxtOff = (1 - cur) * ABUFB2;
            const __half* kp = base + (size_t)(kv1 + sr) * QKV_COLS + Cc + h * HDc + sc;
            const __half* vp = vtb + (size_t)sr * Tc + kv1 + sc;
            cp16(kDst + nxtOff,      kp);  cp16(kDst + nxtOff + 16, kp + 8);
            cp16(kDst + nxtOff + 32, kp + 16); cp16(kDst + nxtOff + 48, kp + 24);
            cp16(vDst + nxtOff,      vp);  cp16(vDst + nxtOff + 16, vp + 8);
            cp16(vDst + nxtOff + 32, vp + 16); cp16(vDst + nxtOff + 48, vp + 24);
            cp_commit();
        }

        // ---- S = Q @ K^T ----
        float S[8][4];
#pragma unroll
        for (int e = 0; e < 8; e++)
#pragma unroll
            for (int i = 0; i < 4; i++) S[e][i] = 0.0f;

#pragma unroll
        for (int kb = 0; kb < 4; kb++) {
            unsigned bfr[8][2];
#pragma unroll
            for (int p = 0; p < 4; p++) {
                unsigned tmp[4];
                ldsm_x4(tmp, kFrag + curOff + p * (16 * ASTRH * 2) + kb * 32);
                bfr[2 * p][0]     = tmp[0]; bfr[2 * p][1]     = tmp[1];
                bfr[2 * p + 1][0] = tmp[2]; bfr[2 * p + 1][1] = tmp[3];
            }
#pragma unroll
            for (int e = 0; e < 8; e++)
                mma_f16(S[e], qf[kb], bfr[e]);
        }

        // ---- Causal mask (diagonal tile) ----
        if (kt == qt) {
#pragma unroll
            for (int e = 0; e < 8; e++) {
                const int j = e * 8 + 2 * t4;
                if (j > r0w)         S[e][0] = -1e30f;
                if (j + 1 > r0w)     S[e][1] = -1e30f;
                if (j > r0w + 8)     S[e][2] = -1e30f;
                if (j + 1 > r0w + 8) S[e][3] = -1e30f;
            }
        }

        // ---- Online softmax ----
        float tm0 = -1e30f, tm1 = -1e30f;
#pragma unroll
        for (int e = 0; e < 8; e++) {
            tm0 = fmaxf(tm0, fmaxf(S[e][0], S[e][1]));
            tm1 = fmaxf(tm1, fmaxf(S[e][2], S[e][3]));
        }
        tm0 = fmaxf(tm0, __shfl_xor_sync(0xffffffffu, tm0, 1));
        tm0 = fmaxf(tm0, __shfl_xor_sync(0xffffffffu, tm0, 2));
        tm1 = fmaxf(tm1, __shfl_xor_sync(0xffffffffu, tm1, 1));
        tm1 = fmaxf(tm1, __shfl_xor_sync(0xffffffffu, tm1, 2));

        const float nm0 = fmaxf(m0, tm0);
        const float nm1 = fmaxf(m1, tm1);
        const float al0 = __expf(m0 - nm0);
        const float al1 = __expf(m1 - nm1);

        float ts0 = 0.0f, ts1 = 0.0f;
#pragma unroll
        for (int e = 0; e < 8; e++) {
            S[e][0] = __expf(S[e][0] - nm0);
            S[e][1] = __expf(S[e][1] - nm0);
            S[e][2] = __expf(S[e][2] - nm1);
            S[e][3] = __expf(S[e][3] - nm1);
            ts0 += S[e][0] + S[e][1];
            ts1 += S[e][2] + S[e][3];
        }
        ts0 += __shfl_xor_sync(0xffffffffu, ts0, 1);
        ts0 += __shfl_xor_sync(0xffffffffu, ts0, 2);
        ts1 += __shfl_xor_sync(0xffffffffu, ts1, 1);
        ts1 += __shfl_xor_sync(0xffffffffu, ts1, 2);

        l0 = l0 * al0 + ts0;
        l1 = l1 * al1 + ts1;
        m0 = nm0;
        m1 = nm1;

#pragma unroll
        for (int e = 0; e < 8; e++) {
            O[e][0] *= al0; O[e][1] *= al0;
            O[e][2] *= al1; O[e][3] *= al1;
        }

        __syncthreads();   // all warps finished reading K tile

        // ---- Store P (fp16) into warp-private rows of Ks[cur] ----
#pragma unroll
        for (int e = 0; e < 8; e++) {
            const int c = e * 8 + 2 * t4;
            *(__half2*)(&Ks[cur * ABUFH + r0w * ASTRH + c]) =
                __floats2half2_rn(S[e][0], S[e][1]);
            *(__half2*)(&Ks[cur * ABUFH + (r0w + 8) * ASTRH + c]) =
                __floats2half2_rn(S[e][2], S[e][3]);
        }
        __syncwarp();

        // ---- O += P @ V ----
#pragma unroll
        for (int kb = 0; kb < 4; kb++) {
            unsigned af[4];
            ldsm_x4(af, qpFrag + curOff + kb * 32);
            unsigned bfr[8][2];
#pragma unroll
            for (int p = 0; p < 4; p++) {
                unsigned tmp[4];
                ldsm_x4(tmp, vFrag + curOff + p * (16 * ASTRH * 2) + kb * 32);
                bfr[2 * p][0]     = tmp[0]; bfr[2 * p][1]     = tmp[1];
                bfr[2 * p + 1][0] = tmp[2]; bfr[2 * p + 1][1] = tmp[3];
            }
#pragma unroll
            for (int e = 0; e < 8; e++)
                mma_f16(O[e], af, bfr[e]);
        }
    }

    // ---- Epilogue: normalize, write y as fp16 ----
    const float inv0 = 1.0f / l0;
    const float inv1 = 1.0f / l1;
    const int gr = q0 + r0w;
    __half* yp0 = g_y + (size_t)(b * Tc + gr) * Cc + h * HDc;
    __half* yp1 = g_y + (size_t)(b * Tc + gr + 8) * Cc + h * HDc;
#pragma unroll
    for (int e = 0; e < 8; e++) {
        const int c = e * 8 + 2 * t4;
        *(__half2*)(yp0 + c) = __floats2half2_rn(O[e][0] * inv0, O[e][1] * inv0);
        *(__half2*)(yp1 + c) = __floats2half2_rn(O[e][2] * inv1, O[e][3] * inv1);
    }
}

extern "C" void kernel_launch(void* const* d_in, const int* in_sizes, int n_in,
                              void* d_out, int out_size)
{
    const float* x      = (const float*)d_in[0];
    const float* w_attn = (const float*)d_in[1];
    const float* b_attn = (const float*)d_in[2];
    const float* w_proj = (const float*)d_in[3];
    const float* b_proj = (const float*)d_in[4];
    float* out = (float*)d_out;

    static bool attr_done = false;
    if (!attr_done) {
        cudaFuncSetAttribute(qkv_f16, cudaFuncAttributeMaxDynamicSharedMemorySize, GEMM_SMEM);
        cudaFuncSetAttribute(proj_f16, cudaFuncAttributeMaxDynamicSharedMemorySize, GEMM_SMEM);
        cudaFuncSetAttribute(attn_tc, cudaFuncAttributeMaxDynamicSharedMemorySize, ATT_SMEM);
        attr_done = true;
    }

    // Convert inputs to fp16 (single launch)
    {
        const int total = N4_X + N4_WA + N4_WP;
        conv3_kernel<<<(total + 255) / 256, 256>>>(x, w_attn, w_proj);
    }
    {
        dim3 grid(QKV_COLS / 128, M_ROWS / 128);
        qkv_f16<<<grid, 256, GEMM_SMEM>>>(b_attn);
    }
    {
        dim3 grid(Bc * Hc, Tc / 64);
        attn_tc<<<grid, 128, ATT_SMEM>>>();
    }
    {
        dim3 grid(Cc / 128, M_ROWS / 128);
        proj_f16<<<grid, 256, GEMM_SMEM>>>(b_proj, out);
    }
}